// round 6
// baseline (speedup 1.0000x reference)
#include <cuda_runtime.h>
#include <cstdint>

constexpr int N_IN  = 256;
constexpr int BATCH = 4096;
constexpr int ITER  = 8;
constexpr int TPB   = 256;   // 128 matrices * 2 row-pairs per block
constexpr int HALF  = 128;   // matrices per block

struct V8 { uint32_t r[8]; };

__device__ __forceinline__ V8 ldg256_el(const void* p) {
    V8 v;
    asm volatile("ld.global.nc.L2::evict_last.v8.b32 {%0,%1,%2,%3,%4,%5,%6,%7}, [%8];"
                 : "=r"(v.r[0]), "=r"(v.r[1]), "=r"(v.r[2]), "=r"(v.r[3]),
                   "=r"(v.r[4]), "=r"(v.r[5]), "=r"(v.r[6]), "=r"(v.r[7])
                 : "l"(p));
    return v;
}
__device__ __forceinline__ void stg256_ef(void* p, const V8& v) {
    asm volatile("st.global.L2::evict_first.v8.b32 [%0], {%1,%2,%3,%4,%5,%6,%7,%8};"
                 :: "l"(p),
                    "r"(v.r[0]), "r"(v.r[1]), "r"(v.r[2]), "r"(v.r[3]),
                    "r"(v.r[4]), "r"(v.r[5]), "r"(v.r[6]), "r"(v.r[7])
                 : "memory");
}

__global__ void __launch_bounds__(TPB) fused_kernel(
    const float* __restrict__ I,
    const float* __restrict__ aW,
    const float* __restrict__ uW,
    const float* __restrict__ tW,
    float* __restrict__ O)
{
    const int tid = threadIdx.x;
    const int h   = blockIdx.x & 1;           // which half of N_IN
    const int g   = blockIdx.x >> 1;          // batch group (0..511)

    // ---- every thread builds its WM[n] in registers (no smem, no sync) ----
    const int n = h * HALF + (tid >> 1);

    float a  = aW[n];
    float ux = 1.0f / (1.0f + __expf(-uW[n * 3 + 0]));
    float uy = 1.0f / (1.0f + __expf(-uW[n * 3 + 1]));
    float uz = 1.0f / (1.0f + __expf(-uW[n * 3 + 2]));
    float inv = rsqrtf(ux * ux + uy * uy + uz * uz);
    ux *= inv; uy *= inv; uz *= inv;

    float s = __sinf(a);
    float c = __cosf(a);

    float4 r0, r1, r2, r3;
    r0.x = (1.0f - ux * ux) * c + ux * ux;
    r0.y = -uz * s - ux * uy * c + ux * uy;
    r0.z =  uy * s - ux * uz * c + ux * uz;
    r0.w = tW[n * 3 + 0];
    r1.x =  uz * s - ux * uy * c + ux * uy;
    r1.y = (1.0f - uy * uy) * c + uy * uy;
    r1.z = -ux * s - uy * uz * c + uy * uz;
    r1.w = tW[n * 3 + 1];
    r2.x = -uy * s - ux * uz * c + ux * uz;
    r2.y =  ux * s - uy * uz * c + uy * uz;
    r2.z = (1.0f - uz * uz) * c + uz * uz;
    r2.w = tW[n * 3 + 2];
    r3 = make_float4(0.0f, 0.0f, 0.0f, 1.0f);

    // ---- stream ITER batches, one 32B load/store per iteration, MLP=4 ----
    constexpr int STRIDE_F = N_IN * 16;        // 4096 floats per batch
    int fidx = g * (ITER * STRIDE_F) + n * 16 + (tid & 1) * 8;

#pragma unroll
    for (int jj = 0; jj < ITER / 4; jj++) {
        V8 a0 = ldg256_el(I + fidx);
        V8 a1 = ldg256_el(I + fidx + STRIDE_F);
        V8 a2 = ldg256_el(I + fidx + 2 * STRIDE_F);
        V8 a3 = ldg256_el(I + fidx + 3 * STRIDE_F);

        V8 in[4] = {a0, a1, a2, a3};
#pragma unroll
        for (int k = 0; k < 4; k++) {
            V8 ov;
#pragma unroll
            for (int half = 0; half < 2; half++) {
                float vx = __uint_as_float(in[k].r[half * 4 + 0]);
                float vy = __uint_as_float(in[k].r[half * 4 + 1]);
                float vz = __uint_as_float(in[k].r[half * 4 + 2]);
                float vw = __uint_as_float(in[k].r[half * 4 + 3]);
                float ox = fmaf(vx, r0.x, fmaf(vy, r1.x, fmaf(vz, r2.x, vw * r3.x)));
                float oy = fmaf(vx, r0.y, fmaf(vy, r1.y, fmaf(vz, r2.y, vw * r3.y)));
                float oz = fmaf(vx, r0.z, fmaf(vy, r1.z, fmaf(vz, r2.z, vw * r3.z)));
                float ow = fmaf(vx, r0.w, fmaf(vy, r1.w, fmaf(vz, r2.w, vw * r3.w)));
                ov.r[half * 4 + 0] = __float_as_uint(ox);
                ov.r[half * 4 + 1] = __float_as_uint(oy);
                ov.r[half * 4 + 2] = __float_as_uint(oz);
                ov.r[half * 4 + 3] = __float_as_uint(ow);
            }
            stg256_ef(O + fidx + k * STRIDE_F, ov);
        }
        fidx += 4 * STRIDE_F;
    }
}

extern "C" void kernel_launch(void* const* d_in, const int* in_sizes, int n_in,
                              void* d_out, int out_size) {
    const float* I  = (const float*)d_in[0];
    const float* aW = (const float*)d_in[1];
    const float* uW = (const float*)d_in[2];
    const float* tW = (const float*)d_in[3];

    int blocks = (BATCH / ITER) * 2;   // 1024
    fused_kernel<<<blocks, TPB>>>(I, aW, uW, tW, (float*)d_out);
}